// round 17
// baseline (speedup 1.0000x reference)
#include <cuda_runtime.h>
#include <cuda_bf16.h>
#include <cstdint>

// Problem constants
#define V   30000
#define D   300
#define H   4
#define C   300
#define HC  1200
#define B   2
#define T   800
#define S   2400     // slots per sample: head|rel|tail
#define E   1600
#define ITEMS (E+S)
#define NEG 0.2f

// Padded GEMM dims
#define MP     4864          // 38 M-tiles of 128
#define KPA    1216          // max padded K
#define NBROWS 2432          // 19 N-tiles of 128
#define XLRW   2400          // fused xl|xr row width

// ---------------- scratch (static __device__, no allocation) ----------------
__device__ int      g_nodes[B*S];
__device__ int      g_rep[B*V];
__device__ int      g_dr[B*ITEMS];
__device__ int      g_src[B*ITEMS];
__device__ int      g_deg[B*S];
__device__ int      g_cur[B*S];
__device__ int      g_roff[B*S + 1];
__device__ int      g_items[B*ITEMS];
__device__ float    g_xlr[(size_t)B*S*XLRW];
__device__ float    g_logit[B*ITEMS*H];
__device__ float    g_ex[B*ITEMS*H];          // normalized alpha
__device__ float    g_w[(size_t)B*S*C];
__device__ __nv_bfloat16 g_ah[(size_t)MP*KPA];
__device__ __nv_bfloat16 g_al[(size_t)MP*KPA];
__device__ __nv_bfloat16 g_bh[(size_t)NBROWS*KPA];
__device__ __nv_bfloat16 g_bl[(size_t)NBROWS*KPA];
__device__ __nv_bfloat16 g_w1h[(size_t)MP*320];
__device__ __nv_bfloat16 g_w1l[(size_t)MP*320];

// ---------------- mma.sync helpers ----------------
__device__ __forceinline__ uint32_t smem_u32(const void* p) {
    uint32_t a;
    asm("{ .reg .u64 t; cvta.to.shared.u64 t, %1; cvt.u32.u64 %0, t; }"
        : "=r"(a) : "l"(p));
    return a;
}
__device__ __forceinline__ void ldmx4(uint32_t* r, uint32_t addr) {
    asm volatile("ldmatrix.sync.aligned.m8n8.x4.shared.b16 {%0,%1,%2,%3}, [%4];"
                 : "=r"(r[0]), "=r"(r[1]), "=r"(r[2]), "=r"(r[3]) : "r"(addr));
}
#define MMA16816(d, a, b) \
    asm volatile("mma.sync.aligned.m16n8k16.row.col.f32.bf16.bf16.f32 " \
                 "{%0,%1,%2,%3}, {%4,%5,%6,%7}, {%8,%9}, {%0,%1,%2,%3};" \
                 : "+f"((d)[0]), "+f"((d)[1]), "+f"((d)[2]), "+f"((d)[3]) \
                 : "r"((a)[0]), "r"((a)[1]), "r"((a)[2]), "r"((a)[3]), \
                   "r"((b)[0]), "r"((b)[1]))
__device__ __forceinline__ void cp16(uint32_t saddr, const void* gptr) {
    asm volatile("cp.async.cg.shared.global [%0], [%1], 16;"
                 :: "r"(saddr), "l"(gptr));
}

// ---------------- HMMA GEMM: cp.async 2-stage, term-major MMA ordering ------
#define TSTRIDE 40
#define TILE_B  (128*TSTRIDE*2)
#define BUF_B   (4*TILE_B)
#define GSMEM   (2*BUF_B)
__global__ void __launch_bounds__(256, 2)
gemm_mma(const __nv_bfloat16* __restrict__ Ah, const __nv_bfloat16* __restrict__ Al,
         int lda,
         const float* __restrict__ bias0, const float* __restrict__ bias1, int nsplit,
         float* __restrict__ Cf, int ldc,
         __nv_bfloat16* __restrict__ Oh, __nv_bfloat16* __restrict__ Ol, int ldo,
         int M, int N, int kchunks)
{
    extern __shared__ char smem[];
    uint32_t sb = smem_u32(smem);

    int tid = threadIdx.x, wid = tid >> 5, lane = tid & 31;
    int bm = blockIdx.y * 128, bn = blockIdx.x * 128;
    int wm = (wid >> 1) * 32;
    int wn = (wid & 1) * 64;

    int lrow0 = tid >> 2, lc8 = (tid & 3) * 8;

    uint32_t laneA = (uint32_t)(((lane & 7) + ((lane >> 3) & 1) * 8) * (TSTRIDE*2)
                                + (lane >> 4) * 16);
    uint32_t laneB = (uint32_t)(((lane & 7) + (lane >> 4) * 8) * (TSTRIDE*2)
                                + ((lane >> 3) & 1) * 16);

    float acc[2][8][4];
    #pragma unroll
    for (int mi = 0; mi < 2; mi++)
        #pragma unroll
        for (int nj = 0; nj < 8; nj++)
            #pragma unroll
            for (int q = 0; q < 4; q++) acc[mi][nj][q] = 0.f;

    auto prefetch = [&](int ch, int buf) {
        int k0 = ch * 32;
        uint32_t base = sb + buf * BUF_B;
        #pragma unroll
        for (int i = 0; i < 2; i++) {
            int row = lrow0 + i * 64;
            uint32_t so = (uint32_t)(row * (TSTRIDE*2) + lc8 * 2);
            size_t ga = (size_t)(bm + row) * lda + k0 + lc8;
            size_t gb = (size_t)(bn + row) * KPA + k0 + lc8;
            cp16(base + so,              Ah + ga);
            cp16(base + TILE_B + so,     Al + ga);
            cp16(base + 2*TILE_B + so,   g_bh + gb);
            cp16(base + 3*TILE_B + so,   g_bl + gb);
        }
        asm volatile("cp.async.commit_group;");
    };

    prefetch(0, 0);

    for (int ch = 0; ch < kchunks; ch++) {
        asm volatile("cp.async.wait_group 0;");
        __syncthreads();                       // data visible + buffer safe
        if (ch + 1 < kchunks) prefetch(ch + 1, (ch + 1) & 1);

        uint32_t base = sb + (ch & 1) * BUF_B;
        uint32_t uAh = base, uAl = base + TILE_B;
        uint32_t uBh = base + 2*TILE_B, uBl = base + 3*TILE_B;

        #pragma unroll
        for (int kk = 0; kk < 2; kk++) {
            uint32_t ah[2][4], al[2][4];
            #pragma unroll
            for (int mi = 0; mi < 2; mi++) {
                uint32_t off = (uint32_t)((wm + mi*16) * (TSTRIDE*2) + kk*32) + laneA;
                ldmx4(ah[mi], uAh + off);
                ldmx4(al[mi], uAl + off);
            }
            // B fragments double-buffered across g
            uint32_t bh[2][4], bl[2][4];
            {
                uint32_t off = (uint32_t)((wn) * (TSTRIDE*2) + kk*32) + laneB;
                ldmx4(bh[0], uBh + off);
                ldmx4(bl[0], uBl + off);
            }
            #pragma unroll
            for (int g = 0; g < 4; g++) {
                int cur = g & 1, nxt = cur ^ 1;
                if (g < 3) {
                    uint32_t off = (uint32_t)((wn + (g+1)*16) * (TSTRIDE*2) + kk*32)
                                   + laneB;
                    ldmx4(bh[nxt], uBh + off);
                    ldmx4(bl[nxt], uBl + off);
                }
                // term-major: same-acc reuse distance = 4 independent MMAs
                #pragma unroll
                for (int mi = 0; mi < 2; mi++)
                    #pragma unroll
                    for (int t = 0; t < 2; t++)
                        MMA16816(acc[mi][g*2+t], ah[mi], bh[cur] + t*2);
                #pragma unroll
                for (int mi = 0; mi < 2; mi++)
                    #pragma unroll
                    for (int t = 0; t < 2; t++)
                        MMA16816(acc[mi][g*2+t], ah[mi], bl[cur] + t*2);
                #pragma unroll
                for (int mi = 0; mi < 2; mi++)
                    #pragma unroll
                    for (int t = 0; t < 2; t++)
                        MMA16816(acc[mi][g*2+t], al[mi], bh[cur] + t*2);
            }
        }
    }

    #pragma unroll
    for (int mi = 0; mi < 2; mi++) {
        #pragma unroll
        for (int nj = 0; nj < 8; nj++) {
            int col = bn + wn + nj*8 + (lane & 3)*2;
            if (col >= N) continue;
            float bv0 = 0.f, bv1 = 0.f;
            if (bias0) {
                bv0 = (col   < nsplit) ? bias0[col]   : bias1[col   - nsplit];
                bv1 = (col+1 < nsplit) ? bias0[col+1] : bias1[col+1 - nsplit];
            }
            int rbase = bm + wm + mi*16 + (lane >> 2);
            #pragma unroll
            for (int hf = 0; hf < 2; hf++) {
                int r = rbase + hf*8;
                if (r >= M) continue;
                float v0 = acc[mi][nj][hf*2]   + bv0;
                float v1 = acc[mi][nj][hf*2+1] + bv1;
                if (Cf) {
                    Cf[(size_t)r * ldc + col]     = v0;
                    Cf[(size_t)r * ldc + col + 1] = v1;
                }
                if (Oh) {
                    __nv_bfloat16 h0 = __float2bfloat16(v0);
                    __nv_bfloat16 h1 = __float2bfloat16(v1);
                    size_t o = (size_t)r * ldo + col;
                    Oh[o]   = h0;
                    Ol[o]   = __float2bfloat16(v0 - __bfloat162float(h0));
                    Oh[o+1] = h1;
                    Ol[o+1] = __float2bfloat16(v1 - __bfloat162float(h1));
                }
            }
        }
    }
}

// ---------------- setup / split kernels ----------------
__device__ __forceinline__ void split_write(__nv_bfloat16* ph, __nv_bfloat16* pl,
                                            size_t idx, float v) {
    __nv_bfloat16 h = __float2bfloat16(v);
    ph[idx] = h;
    pl[idx] = __float2bfloat16(v - __bfloat162float(h));
}

// fused: nodes + rep init + degree/cursor init
__global__ void k_setup(const int* __restrict__ kg) {
    int i = blockIdx.x*blockDim.x + threadIdx.x;
    if (i < B*V) g_rep[i] = 0x7FFFFFFF;
    if (i < B*S) {
        int b = i / S, s = i % S;
        int t = s % T, col = s / T;
        g_nodes[i] = kg[(b*T + t)*3 + col];
        g_deg[i] = 0; g_cur[i] = 0;
    }
}
__global__ void k_repmin() {
    int i = blockIdx.x*blockDim.x + threadIdx.x;
    if (i >= B*S) return;
    int b = i / S, s = i % S;
    atomicMin(&g_rep[b*V + g_nodes[i]], s);
}

// item -> (src slot, dst rep) ; count degrees   (once; reused both layers)
__global__ void k_dr() {
    int it = blockIdx.x*blockDim.x + threadIdx.x;
    if (it >= B*ITEMS) return;
    int b = it / ITEMS, j = it % ITEMS;
    int src, dr;
    if (j < E) {
        src = j;
        dr = g_rep[b*V + g_nodes[b*S + j + 800]];
    } else {
        int s = j - E;
        src = s;
        dr = (g_rep[b*V + g_nodes[b*S + s]] == s) ? s : -1;
    }
    g_src[it] = src;
    g_dr[it] = dr;
    if (dr >= 0) atomicAdd(&g_deg[b*S + dr], 1);
}

// exclusive scan of g_deg -> g_roff (single block)
__global__ void k_scan() {
    __shared__ int ssum[256];
    int t = threadIdx.x;
    const int CH = (B*S + 255) / 256;
    int base = t * CH, s = 0;
    for (int i = 0; i < CH; i++)
        if (base + i < B*S) s += g_deg[base + i];
    ssum[t] = s;
    __syncthreads();
    if (t == 0) {
        int acc = 0;
        for (int i = 0; i < 256; i++) { int v = ssum[i]; ssum[i] = acc; acc += v; }
        g_roff[B*S] = acc;
    }
    __syncthreads();
    int acc = ssum[t];
    for (int i = 0; i < CH; i++) {
        int idx = base + i;
        if (idx < B*S) { g_roff[idx] = acc; acc += g_deg[idx]; }
    }
}
__global__ void k_fill() {
    int it = blockIdx.x*blockDim.x + threadIdx.x;
    if (it >= B*ITEMS) return;
    int dr = g_dr[it];
    if (dr < 0) return;
    int row = (it / ITEMS) * S + dr;
    int p = atomicAdd(&g_cur[row], 1);
    g_items[g_roff[row] + p] = it;
}

// coalesced transpose+split: g_b{h,l}[n,k] = W[k, n] (optionally concat W1)
__global__ void tw_split_t(const float* __restrict__ W0, const float* __restrict__ W1,
                           int K, int N) {
    __shared__ float s[32][33];
    int k0 = blockIdx.x * 32, n0 = blockIdx.y * 32;
    #pragma unroll
    for (int i = 0; i < 4; i++) {
        int k = k0 + threadIdx.y + i*8;
        int n = n0 + threadIdx.x;
        float v = 0.f;
        if (k < K) {
            if (n < N) v = W0[(size_t)k*N + n];
            else if (W1 && n < 2*N) v = W1[(size_t)k*N + (n - N)];
        }
        s[threadIdx.y + i*8][threadIdx.x] = v;
    }
    __syncthreads();
    #pragma unroll
    for (int i = 0; i < 4; i++) {
        int n = n0 + threadIdx.y + i*8;
        int k = k0 + threadIdx.x;
        split_write(g_bh, g_bl, (size_t)n*KPA + k, s[threadIdx.x][threadIdx.y + i*8]);
    }
}

// A = gathered embeddings, lda=320
__global__ void split_emb(const float* __restrict__ emb) {
    int i = blockIdx.x*blockDim.x + threadIdx.x;
    if (i >= MP*320) return;
    int row = i / 320, k = i % 320;
    float v = 0.f;
    if (row < B*S && k < D) v = emb[(size_t)g_nodes[row]*D + k];
    split_write(g_ah, g_al, (size_t)i, v);
}

__global__ void zero_w1() {
    int i = blockIdx.x*blockDim.x + threadIdx.x;
    if (i >= MP*320) return;
    g_w1h[i] = __float2bfloat16(0.f);
    g_w1l[i] = __float2bfloat16(0.f);
}

// cat A tile for final GEMM: lda=960, rows 1664
__global__ void split_cat() {
    int i = blockIdx.x*blockDim.x + threadIdx.x;
    if (i >= 1664*960) return;
    int row = i / 960, k = i % 960;
    float v = 0.f;
    if (row < B*T && k < 3*C) {
        int b = row / T, t = row % T;
        int part = k / C, c = k % C;
        v = g_w[(size_t)(b*S + part*T + t)*C + c];
    }
    split_write(g_ah, g_al, (size_t)i, v);
}

// ---------------- attention (CSR gather, no atomics) ----------------
__global__ void k_logits(const float* __restrict__ att) {
    int it = (blockIdx.x*blockDim.x + threadIdx.x) >> 5;
    int lane = threadIdx.x & 31;
    if (it >= B*ITEMS) return;
    if (g_dr[it] < 0) return;
    int b = it / ITEMS, j = it % ITEMS;
    int src = g_src[it];
    int dst = (j < E) ? j + 800 : src;

    const float* xl = g_xlr + (size_t)(b*S + src) * XLRW;
    const float* xr = g_xlr + (size_t)(b*S + dst) * XLRW + HC;
    #pragma unroll
    for (int h = 0; h < H; h++) {
        float acc = 0.f;
        for (int c = lane; c < C; c += 32) {
            float v = xl[h*C + c] + xr[h*C + c];
            v = (v > 0.f) ? v : NEG * v;
            acc += v * att[h*C + c];
        }
        #pragma unroll
        for (int off = 16; off; off >>= 1)
            acc += __shfl_down_sync(0xffffffffu, acc, off);
        if (lane == 0) g_logit[it*H + h] = acc;
    }
}

// per (dst-rep row, head): softmax over CSR list -> alpha in g_ex
__global__ void k_soft() {
    int id = blockIdx.x*blockDim.x + threadIdx.x;
    if (id >= B*S*H) return;
    int row = id / H, h = id % H;
    int s0 = g_roff[row], s1 = g_roff[row + 1];
    if (s0 == s1) return;
    float m = -3.4e38f;
    for (int e = s0; e < s1; e++)
        m = fmaxf(m, g_logit[g_items[e]*H + h]);
    float den = 0.f;
    for (int e = s0; e < s1; e++)
        den += expf(g_logit[g_items[e]*H + h] - m);
    for (int e = s0; e < s1; e++) {
        int it = g_items[e];
        g_ex[it*H + h] = expf(g_logit[it*H + h] - m) / den;
    }
}

// fused: gather-aggregate + bias + relu + bf16 split into A buffer (lda=KPA)
__global__ void k_hsplit(const float* __restrict__ bias) {
    int row = blockIdx.x;                 // 0..MP-1
    int t = threadIdx.x;                  // 256
    if (row >= B*S) {
        for (int c = t; c < KPA; c += 256)
            split_write(g_ah, g_al, (size_t)row*KPA + c, 0.f);
        return;
    }
    int b = row / S;
    int r = g_rep[b*V + g_nodes[row]];
    int gr = b*S + r;
    int s0 = g_roff[gr], s1 = g_roff[gr + 1];
    for (int c = t; c < KPA; c += 256) {
        float v = 0.f;
        if (c < HC) {
            v = bias[c];
            int h = c / C;
            for (int e = s0; e < s1; e++) {
                int it = g_items[e];
                float a = g_ex[it*H + h];
                int src = g_src[it];
                v += a * g_xlr[(size_t)(b*S + src) * XLRW + c];
            }
            v = fmaxf(v, 0.f);
        }
        split_write(g_ah, g_al, (size_t)row*KPA + c, v);
    }
}

// ---------------- driver ----------------
extern "C" void kernel_launch(void* const* d_in, const int* in_sizes, int n_in,
                              void* d_out, int out_size) {
    const int*   kg    = (const int*)  d_in[0];
    const float* emb   = (const float*)d_in[1];
    const float* Wl1   = (const float*)d_in[2];
    const float* bl1   = (const float*)d_in[3];
    const float* Wr1   = (const float*)d_in[4];
    const float* br1   = (const float*)d_in[5];
    const float* att1  = (const float*)d_in[6];
    const float* bias1 = (const float*)d_in[7];
    const float* Wl2   = (const float*)d_in[8];
    const float* bl2   = (const float*)d_in[9];
    const float* Wr2   = (const float*)d_in[10];
    const float* br2   = (const float*)d_in[11];
    const float* att2  = (const float*)d_in[12];
    const float* bias2 = (const float*)d_in[13];
    const float* Wp1   = (const float*)d_in[14];
    const float* bp1   = (const float*)d_in[15];
    const float* Wp2   = (const float*)d_in[16];
    const float* bp2   = (const float*)d_in[17];
    const float* Wlii  = (const float*)d_in[18];
    float* out = (float*)d_out;

    cudaFuncSetAttribute(gemm_mma, cudaFuncAttributeMaxDynamicSharedMemorySize,
                         GSMEM);

    __nv_bfloat16 *p_ah, *p_al, *p_w1h, *p_w1l;
    float *p_xlr, *p_w;
    cudaGetSymbolAddress((void**)&p_ah,  g_ah);
    cudaGetSymbolAddress((void**)&p_al,  g_al);
    cudaGetSymbolAddress((void**)&p_w1h, g_w1h);
    cudaGetSymbolAddress((void**)&p_w1l, g_w1l);
    cudaGetSymbolAddress((void**)&p_xlr, g_xlr);
    cudaGetSymbolAddress((void**)&p_w,   g_w);

    auto nb = [](long n) { return (int)((n + 255) / 256); };
    dim3 tb(32, 8);

    // ---- GEMM L1 first (ncu capture slot lands here) ----
    k_setup<<<(B*V + 255)/256, 256>>>(kg);
    tw_split_t<<<dim3(320/32, 2432/32), tb>>>(Wl1, Wr1, D, HC);
    split_emb<<<nb(MP*320), 256>>>(emb);
    gemm_mma<<<dim3(19, 38), 256, GSMEM>>>(
        p_ah, p_al, 320, bl1, br1, HC,
        p_xlr, XLRW, nullptr, nullptr, 0, B*S, XLRW, 10);

    // ---- graph structure (once) ----
    k_repmin<<<(B*S + 255)/256, 256>>>();
    k_dr<<<nb(B*ITEMS), 256>>>();
    k_scan<<<1, 256>>>();
    k_fill<<<nb(B*ITEMS), 256>>>();

    int logitBlocks = (B*ITEMS*32 + 127)/128;

    // ---- layer 1 attention ----
    k_logits<<<logitBlocks, 128>>>(att1);
    k_soft<<<nb(B*S*H), 256>>>();
    k_hsplit<<<MP, 256>>>(bias1);

    // ---- layer 2 ----
    tw_split_t<<<dim3(1216/32, 2432/32), tb>>>(Wl2, Wr2, HC, HC);
    gemm_mma<<<dim3(19, 38), 256, GSMEM>>>(
        p_ah, p_al, KPA, bl2, br2, HC,
        p_xlr, XLRW, nullptr, nullptr, 0, B*S, XLRW, 38);
    k_logits<<<logitBlocks, 128>>>(att2);
    k_soft<<<nb(B*S*H), 256>>>();
    k_hsplit<<<MP, 256>>>(bias2);

    // ---- projection 1: w1 = h @ Wp1 + bp1 (bf16-split output) ----
    tw_split_t<<<dim3(1216/32, 384/32), tb>>>(Wp1, nullptr, HC, C);
    zero_w1<<<nb(MP*320), 256>>>();
    gemm_mma<<<dim3(3, 38), 256, GSMEM>>>(
        p_ah, p_al, KPA, bp1, bp1, C,
        nullptr, 0, p_w1h, p_w1l, 320, B*S, C, 38);

    // ---- projection 2: w = w1 @ Wp2 + bp2 (f32 output) ----
    tw_split_t<<<dim3(320/32, 384/32), tb>>>(Wp2, nullptr, C, C);
    gemm_mma<<<dim3(3, 38), 256, GSMEM>>>(
        p_w1h, p_w1l, 320, bp2, bp2, C,
        p_w, C, nullptr, nullptr, 0, B*S, C, 10);

    // ---- concat + final GEMM ----
    split_cat<<<nb(1664*960), 256>>>();
    tw_split_t<<<dim3(960/32, 768/32), tb>>>(Wlii, nullptr, 3*C, 768);
    gemm_mma<<<dim3(6, 13), 256, GSMEM>>>(
        p_ah, p_al, 960, nullptr, nullptr, 768,
        out, 768, nullptr, nullptr, 0, B*T, 768, 30);
}